// round 11
// baseline (speedup 1.0000x reference)
#include <cuda_runtime.h>
#include <cstdint>

// ======================= problem constants =======================
constexpr int MB = 8192;   // batch (GEMM M)
constexpr int NB = 2048;   // out features (GEMM N)
constexpr int KB = 2048;   // in features (GEMM K)

constexpr int BM = 128;
constexpr int BN = 64;
constexpr int BK = 128;            // 128 e4m3 bytes = one smem row
constexpr int KITERS = KB / BK;    // 16
constexpr int NS = 3;

constexpr int STAGE_A = BM * BK;   // 16384
constexpr int STAGE_B = BN * BK;   //  8192
constexpr int SMEM_B_OFF = NS * STAGE_A;            // 49152
constexpr int SMEM_TOTAL = NS * (STAGE_A + STAGE_B); // 73728 (72KB -> 3 CTAs/SM)

// e4m3 sign scratch
__device__ __align__(16) unsigned char g_xf[(size_t)MB * KB];  // 16 MB
__device__ __align__(16) unsigned char g_wf[(size_t)NB * KB];  //  4 MB

// ======================= helpers =======================
__device__ __forceinline__ uint32_t smem_u32(const void* p) {
    uint32_t a;
    asm("{ .reg .u64 t; cvta.to.shared.u64 t, %1; cvt.u32.u64 %0, t; }" : "=r"(a) : "l"(p));
    return a;
}
__device__ __forceinline__ void cp16(uint32_t dst, const void* src) {
    asm volatile("cp.async.cg.shared.global [%0], [%1], 16;" :: "r"(dst), "l"(src));
}
__device__ __forceinline__ void cp_commit() {
    asm volatile("cp.async.commit_group;" ::: "memory");
}
template <int N>
__device__ __forceinline__ void cp_wait() {
    asm volatile("cp.async.wait_group %0;" :: "n"(N) : "memory");
}
__device__ __forceinline__ void ldsm_x4(uint32_t* r, uint32_t addr) {
    asm volatile("ldmatrix.sync.aligned.m8n8.x4.shared.b16 {%0,%1,%2,%3}, [%4];"
        : "=r"(r[0]), "=r"(r[1]), "=r"(r[2]), "=r"(r[3]) : "r"(addr));
}
__device__ __forceinline__ void fmma16832(float* d, const uint32_t* a, const uint32_t* b)
{
    asm volatile(
        "mma.sync.aligned.m16n8k32.row.col.f32.e4m3.e4m3.f32 "
        "{%0,%1,%2,%3}, {%4,%5,%6,%7}, {%8,%9}, {%0,%1,%2,%3};"
        : "+f"(d[0]), "+f"(d[1]), "+f"(d[2]), "+f"(d[3])
        : "r"(a[0]), "r"(a[1]), "r"(a[2]), "r"(a[3]),
          "r"(b[0]), "r"(b[1]));
}

// ======================= quantize: fp32 -> e4m3 sign =======================
// +1 -> 0x38, -1 -> 0xB8, 0 -> 0x00
constexpr int NX16 = MB * KB / 16;
constexpr int NW16 = NB * KB / 16;
constexpr int NT16 = NX16 + NW16;

__global__ void __launch_bounds__(256)
quant_fp8_kernel(const float* __restrict__ x, const float* __restrict__ w,
                 unsigned char* __restrict__ xf, unsigned char* __restrict__ wf)
{
    int i = blockIdx.x * 256 + threadIdx.x;
    if (i >= NT16) return;
    const float4* src;
    uint4* of;
    if (i < NX16) {
        src = reinterpret_cast<const float4*>(x) + (size_t)i * 4;
        of = reinterpret_cast<uint4*>(xf) + i;
    } else {
        int j = i - NX16;
        src = reinterpret_cast<const float4*>(w) + (size_t)j * 4;
        of = reinterpret_cast<uint4*>(wf) + j;
    }
    uint32_t w38[4];
#pragma unroll
    for (int j = 0; j < 4; j++) {
        float4 v = src[j];
        uint32_t f0 = v.x > 0.f ? 0x38u : (v.x < 0.f ? 0xB8u : 0x00u);
        uint32_t f1 = v.y > 0.f ? 0x38u : (v.y < 0.f ? 0xB8u : 0x00u);
        uint32_t f2 = v.z > 0.f ? 0x38u : (v.z < 0.f ? 0xB8u : 0x00u);
        uint32_t f3 = v.w > 0.f ? 0x38u : (v.w < 0.f ? 0xB8u : 0x00u);
        w38[j] = f0 | (f1 << 8) | (f2 << 16) | (f3 << 24);
    }
    *of = make_uint4(w38[0], w38[1], w38[2], w38[3]);
}

// ======================= FP8 GEMM =======================
// out[m,n] = sum_k xf[m,k]*wf[n,k] + bias[n]
// CTA 128x64, 8 warps: warp grid 4(M) x 2(N); warp tile 32 x 32.
// acc = 32 regs/thread -> 85-reg cap -> 3 CTAs/SM (24 warps).
__global__ void __launch_bounds__(256, 3)
tgemm_fp8(const unsigned char* __restrict__ xf, const unsigned char* __restrict__ wf,
          const float* __restrict__ bias, float* __restrict__ out)
{
    extern __shared__ unsigned char smem[];
    const uint32_t sb = smem_u32(smem);

    const int tid  = threadIdx.x;
    const int wid  = tid >> 5;
    const int lane = tid & 31;
    const int tile_m = blockIdx.y;   // 0..63
    const int tile_n = blockIdx.x;   // 0..31
    const int m_off = (wid >> 1) * 32;
    const int n_off = (wid & 1) * 32;

    // ---- per-thread load geometry ----
    const int lr = tid >> 3;        // row 0..31 (stride 32)
    const int lc = tid & 7;         // 16B chunk 0..7
    const unsigned char* agp = xf + (size_t)(tile_m * BM + lr) * KB + lc * 16;
    const unsigned char* bgp = wf + (size_t)(tile_n * BN + lr) * KB + lc * 16;
    const uint32_t dst0 = (uint32_t)(lr * 128 + ((lc ^ (lr & 7)) << 4));

    auto load_stage = [&](int kk, int s) {
        const uint32_t a_s = sb + s * STAGE_A + dst0;
        const uint32_t b_s = sb + SMEM_B_OFF + s * STAGE_B + dst0;
        const unsigned char* ag = agp + kk * BK;
        const unsigned char* bg = bgp + kk * BK;
#pragma unroll
        for (int i = 0; i < 4; i++)                     // A: 128 rows
            cp16(a_s + i * 4096, ag + (size_t)i * 32 * KB);
#pragma unroll
        for (int i = 0; i < 2; i++)                     // B: 64 rows
            cp16(b_s + i * 4096, bg + (size_t)i * 32 * KB);
        cp_commit();
    };

    // ---- ldmatrix lane geometry ----
    const int sub = lane >> 3;
    const int l7  = lane & 7;
    const int a_row0 = m_off + (sub & 1) * 8 + l7;       // + mt*16
    const int a_csel = sub >> 1;
    const int b_rowb = n_off + (sub >> 1) * 8 + l7;      // + p*16
    const int b_csel = sub & 1;

    float acc[2][4][4];
#pragma unroll
    for (int mt = 0; mt < 2; mt++)
#pragma unroll
        for (int nt = 0; nt < 4; nt++)
#pragma unroll
            for (int r = 0; r < 4; r++) acc[mt][nt][r] = 0.f;

    load_stage(0, 0);
    load_stage(1, 1);

    for (int t = 0; t < KITERS; ++t) {
        const int s = t % NS;
        cp_wait<NS - 2>();
        __syncthreads();
        if (t + NS - 1 < KITERS) load_stage(t + NS - 1, (t + NS - 1) % NS);
        else cp_commit();

        const uint32_t a_s = sb + s * STAGE_A;
        const uint32_t b_s = sb + SMEM_B_OFF + s * STAGE_B;

#pragma unroll
        for (int ks = 0; ks < 4; ks++) {
            uint32_t a[2][4];
#pragma unroll
            for (int mt = 0; mt < 2; mt++) {
                const int r = a_row0 + mt * 16;
                const int c = (2 * ks + a_csel) ^ (r & 7);
                ldsm_x4(a[mt], a_s + r * 128 + (c << 4));
            }
#pragma unroll
            for (int p = 0; p < 2; p++) {
                uint32_t b[4];
                const int r = b_rowb + p * 16;
                const int c = (2 * ks + b_csel) ^ (r & 7);
                ldsm_x4(b, b_s + r * 128 + (c << 4));
                fmma16832(acc[0][2 * p],     a[0], b);
                fmma16832(acc[0][2 * p + 1], a[0], b + 2);
                fmma16832(acc[1][2 * p],     a[1], b);
                fmma16832(acc[1][2 * p + 1], a[1], b + 2);
            }
        }
    }

    // ======================= epilogue =======================
    const int qr = lane >> 2;
    const int qc = lane & 3;
    const int gm0 = tile_m * BM + m_off + qr;
    const int gn0 = tile_n * BN + n_off + qc * 2;
#pragma unroll
    for (int mt = 0; mt < 2; mt++) {
#pragma unroll
        for (int nt = 0; nt < 4; nt++) {
            const int col = gn0 + nt * 8;
            const float2 bb = *reinterpret_cast<const float2*>(bias + col);
            const int row0 = gm0 + mt * 16;
            float2 v0, v1;
            v0.x = acc[mt][nt][0] + bb.x;
            v0.y = acc[mt][nt][1] + bb.y;
            v1.x = acc[mt][nt][2] + bb.x;
            v1.y = acc[mt][nt][3] + bb.y;
            *reinterpret_cast<float2*>(out + (size_t)row0 * NB + col) = v0;
            *reinterpret_cast<float2*>(out + (size_t)(row0 + 8) * NB + col) = v1;
        }
    }
}

// ======================= launch =======================
extern "C" void kernel_launch(void* const* d_in, const int* in_sizes, int n_in,
                              void* d_out, int out_size)
{
    const float* x    = (const float*)d_in[0];
    const float* w    = (const float*)d_in[1];
    const float* bias = (const float*)d_in[2];
    float* out = (float*)d_out;

    void* xf; cudaGetSymbolAddress(&xf, g_xf);
    void* wf; cudaGetSymbolAddress(&wf, g_wf);

    quant_fp8_kernel<<<(NT16 + 255) / 256, 256>>>(
        x, w, (unsigned char*)xf, (unsigned char*)wf);

    cudaFuncSetAttribute(tgemm_fp8, cudaFuncAttributeMaxDynamicSharedMemorySize, SMEM_TOTAL);
    tgemm_fp8<<<dim3(NB / BN, MB / BM), 256, SMEM_TOTAL>>>(
        (const unsigned char*)xf, (const unsigned char*)wf, bias, out);
}

// round 12
// speedup vs baseline: 1.2007x; 1.2007x over previous
#include <cuda_runtime.h>
#include <cuda_fp16.h>
#include <cstdint>

// ======================= problem constants =======================
constexpr int MB = 8192;   // batch (GEMM M)
constexpr int NB = 2048;   // out features (GEMM N)
constexpr int KB = 2048;   // in features (GEMM K)

constexpr int BM = 128;
constexpr int BN = 128;
constexpr int BK = 128;            // 128 e4m3 bytes = one smem row
constexpr int KITERS = KB / BK;    // 16
constexpr int NS = 3;

constexpr int STAGE = BM * BK;     // 16384
constexpr int SMEM_B_OFF = NS * STAGE;
constexpr int SMEM_TOTAL = 2 * NS * STAGE;  // 98304

// e4m3 sign scratch
__device__ __align__(16) unsigned char g_xf[(size_t)MB * KB];  // 16 MB
__device__ __align__(16) unsigned char g_wf[(size_t)NB * KB];  //  4 MB

// ======================= helpers =======================
__device__ __forceinline__ uint32_t smem_u32(const void* p) {
    uint32_t a;
    asm("{ .reg .u64 t; cvta.to.shared.u64 t, %1; cvt.u32.u64 %0, t; }" : "=r"(a) : "l"(p));
    return a;
}
__device__ __forceinline__ void cp16(uint32_t dst, const void* src) {
    asm volatile("cp.async.cg.shared.global [%0], [%1], 16;" :: "r"(dst), "l"(src));
}
__device__ __forceinline__ void cp_commit() {
    asm volatile("cp.async.commit_group;" ::: "memory");
}
template <int N>
__device__ __forceinline__ void cp_wait() {
    asm volatile("cp.async.wait_group %0;" :: "n"(N) : "memory");
}
__device__ __forceinline__ void ldsm_x4(uint32_t* r, uint32_t addr) {
    asm volatile("ldmatrix.sync.aligned.m8n8.x4.shared.b16 {%0,%1,%2,%3}, [%4];"
        : "=r"(r[0]), "=r"(r[1]), "=r"(r[2]), "=r"(r[3]) : "r"(addr));
}
// e4m3 x e4m3 -> f16 accumulate (exact for ternary sums |s| <= 2048)
__device__ __forceinline__ void fmma16832_h(uint32_t* d, const uint32_t* a, const uint32_t* b)
{
    asm volatile(
        "mma.sync.aligned.m16n8k32.row.col.f16.e4m3.e4m3.f16 "
        "{%0,%1}, {%2,%3,%4,%5}, {%6,%7}, {%0,%1};"
        : "+r"(d[0]), "+r"(d[1])
        : "r"(a[0]), "r"(a[1]), "r"(a[2]), "r"(a[3]),
          "r"(b[0]), "r"(b[1]));
}

// ======================= quantize: fp32 -> e4m3 sign =======================
// +1 -> 0x38, -1 -> 0xB8, 0 -> 0x00
constexpr int NX16 = MB * KB / 16;
constexpr int NW16 = NB * KB / 16;
constexpr int NT16 = NX16 + NW16;

__global__ void __launch_bounds__(256)
quant_fp8_kernel(const float* __restrict__ x, const float* __restrict__ w,
                 unsigned char* __restrict__ xf, unsigned char* __restrict__ wf)
{
    int i = blockIdx.x * 256 + threadIdx.x;
    if (i >= NT16) return;
    const float4* src;
    uint4* of;
    if (i < NX16) {
        src = reinterpret_cast<const float4*>(x) + (size_t)i * 4;
        of = reinterpret_cast<uint4*>(xf) + i;
    } else {
        int j = i - NX16;
        src = reinterpret_cast<const float4*>(w) + (size_t)j * 4;
        of = reinterpret_cast<uint4*>(wf) + j;
    }
    uint32_t w38[4];
#pragma unroll
    for (int j = 0; j < 4; j++) {
        float4 v = src[j];
        uint32_t f0 = v.x > 0.f ? 0x38u : (v.x < 0.f ? 0xB8u : 0x00u);
        uint32_t f1 = v.y > 0.f ? 0x38u : (v.y < 0.f ? 0xB8u : 0x00u);
        uint32_t f2 = v.z > 0.f ? 0x38u : (v.z < 0.f ? 0xB8u : 0x00u);
        uint32_t f3 = v.w > 0.f ? 0x38u : (v.w < 0.f ? 0xB8u : 0x00u);
        w38[j] = f0 | (f1 << 8) | (f2 << 16) | (f3 << 24);
    }
    *of = make_uint4(w38[0], w38[1], w38[2], w38[3]);
}

// ======================= FP8 GEMM (f16 accumulate) =======================
// out[m,n] = sum_k xf[m,k]*wf[n,k] + bias[n]
// CTA 128x128, 8 warps: warp grid 4(M) x 2(N); warp tile 32 x 64.
// Accumulators are f16x2 (exact: integer sums bounded by K=2048 = 2^11).
__global__ void __launch_bounds__(256, 2)
tgemm_fp8(const unsigned char* __restrict__ xf, const unsigned char* __restrict__ wf,
          const float* __restrict__ bias, float* __restrict__ out)
{
    extern __shared__ unsigned char smem[];
    const uint32_t sb = smem_u32(smem);
    const uint32_t sA = sb;
    const uint32_t sB = sb + SMEM_B_OFF;

    const int tid  = threadIdx.x;
    const int wid  = tid >> 5;
    const int lane = tid & 31;
    const int tile_m = blockIdx.y;
    const int tile_n = blockIdx.x;   // 0..15
    const int m_off = (wid >> 1) * 32;
    const int n_off = (wid & 1) * 64;

    const unsigned char* ag0 = xf + (size_t)tile_m * BM * KB;
    const unsigned char* bg0 = wf + (size_t)tile_n * BN * KB;

    auto load_stage = [&](int kk, int s) {
        const uint32_t a_s = sA + s * STAGE;
        const uint32_t b_s = sB + s * STAGE;
        const unsigned char* ag = ag0 + kk * BK;
        const unsigned char* bg = bg0 + kk * BK;
#pragma unroll
        for (int i = 0; i < 4; i++) {
            int idx = tid + i * 256;
            int r = idx >> 3, c = idx & 7;
            uint32_t d = r * 128 + ((c ^ (r & 7)) << 4);
            cp16(a_s + d, ag + (size_t)r * KB + c * 16);
        }
#pragma unroll
        for (int i = 0; i < 4; i++) {
            int idx = tid + i * 256;
            int r = idx >> 3, c = idx & 7;
            uint32_t d = r * 128 + ((c ^ (r & 7)) << 4);
            cp16(b_s + d, bg + (size_t)r * KB + c * 16);
        }
        cp_commit();
    };

    const int sub = lane >> 3;
    const int l7  = lane & 7;
    const int a_row0 = m_off + (sub & 1) * 8 + l7;
    const int a_csel = sub >> 1;
    const int b_rowb = n_off + (sub >> 1) * 8 + l7;
    const int b_csel = sub & 1;

    // f16x2 accumulators: [mt][nt][2] -> 32 regs total
    uint32_t acc[2][8][2];
#pragma unroll
    for (int mt = 0; mt < 2; mt++)
#pragma unroll
        for (int nt = 0; nt < 8; nt++) {
            acc[mt][nt][0] = 0u;
            acc[mt][nt][1] = 0u;
        }

    load_stage(0, 0);
    load_stage(1, 1);

    for (int t = 0; t < KITERS; ++t) {
        const int s = t % NS;
        cp_wait<NS - 2>();
        __syncthreads();
        if (t + NS - 1 < KITERS) load_stage(t + NS - 1, (t + NS - 1) % NS);
        else cp_commit();

        const uint32_t a_s = sA + s * STAGE;
        const uint32_t b_s = sB + s * STAGE;
#pragma unroll
        for (int ks = 0; ks < 4; ks++) {
            uint32_t a[2][4];
#pragma unroll
            for (int mt = 0; mt < 2; mt++) {
                const int r = a_row0 + mt * 16;
                const int c = (2 * ks + a_csel) ^ (r & 7);
                ldsm_x4(a[mt], a_s + r * 128 + (c << 4));
            }
#pragma unroll
            for (int p = 0; p < 4; p++) {
                uint32_t b[4];
                const int r = b_rowb + p * 16;
                const int c = (2 * ks + b_csel) ^ (r & 7);
                ldsm_x4(b, b_s + r * 128 + (c << 4));
                fmma16832_h(acc[0][2 * p],     a[0], b);
                fmma16832_h(acc[0][2 * p + 1], a[0], b + 2);
                fmma16832_h(acc[1][2 * p],     a[1], b);
                fmma16832_h(acc[1][2 * p + 1], a[1], b + 2);
            }
        }
    }

    // ======================= epilogue =======================
    const int qr = lane >> 2;
    const int qc = lane & 3;
    const int gm0 = tile_m * BM + m_off + qr;
    const int gn0 = tile_n * BN + n_off + qc * 2;
#pragma unroll
    for (int mt = 0; mt < 2; mt++) {
#pragma unroll
        for (int nt = 0; nt < 8; nt++) {
            const int col = gn0 + nt * 8;
            const float2 bb = *reinterpret_cast<const float2*>(bias + col);
            const int row0 = gm0 + mt * 16;
            const __half2 h0 = *reinterpret_cast<const __half2*>(&acc[mt][nt][0]);
            const __half2 h1 = *reinterpret_cast<const __half2*>(&acc[mt][nt][1]);
            const float2 f0 = __half22float2(h0);
            const float2 f1 = __half22float2(h1);
            float2 v0, v1;
            v0.x = f0.x + bb.x;
            v0.y = f0.y + bb.y;
            v1.x = f1.x + bb.x;
            v1.y = f1.y + bb.y;
            *reinterpret_cast<float2*>(out + (size_t)row0 * NB + col) = v0;
            *reinterpret_cast<float2*>(out + (size_t)(row0 + 8) * NB + col) = v1;
        }
    }
}

// ======================= launch =======================
extern "C" void kernel_launch(void* const* d_in, const int* in_sizes, int n_in,
                              void* d_out, int out_size)
{
    const float* x    = (const float*)d_in[0];
    const float* w    = (const float*)d_in[1];
    const float* bias = (const float*)d_in[2];
    float* out = (float*)d_out;

    void* xf; cudaGetSymbolAddress(&xf, g_xf);
    void* wf; cudaGetSymbolAddress(&wf, g_wf);

    quant_fp8_kernel<<<(NT16 + 255) / 256, 256>>>(
        x, w, (unsigned char*)xf, (unsigned char*)wf);

    cudaFuncSetAttribute(tgemm_fp8, cudaFuncAttributeMaxDynamicSharedMemorySize, SMEM_TOTAL);
    tgemm_fp8<<<dim3(NB / BN, MB / BM), 256, SMEM_TOTAL>>>(
        (const unsigned char*)xf, (const unsigned char*)wf, bias, out);
}